// round 1
// baseline (speedup 1.0000x reference)
#include <cuda_runtime.h>

#define NW 14
#define NSTATE (1 << NW)       // 16384 amplitudes
#define NTHREADS 512
#define NWARPS (NTHREADS / 32)

// Masks describing the CNOT-ring entangler as a GF(2) linear map on basis-state
// indices.  u = A x gives the "virtual" bit values of physical index x after one
// entangler layer; pairs for a gate on virtual bit b differ by column b of A^-1;
// measurement (after two entangler layers) uses rows of A^2.
struct GateMasks {
    int rowA[NW];     // rows of A
    int colAinv[NW];  // columns of A^-1 (pair masks)
    int rowA2[NW];    // rows of A^2 (measurement parity masks)
};

__device__ __forceinline__ float2 cmul(float2 a, float2 b) {
    return make_float2(fmaf(a.x, b.x, -a.y * b.y), fmaf(a.x, b.y, a.y * b.x));
}
__device__ __forceinline__ float2 cmadd(float2 acc, float2 a, float2 b) {
    acc.x = fmaf(a.x, b.x, fmaf(-a.y, b.y, acc.x));
    acc.y = fmaf(a.x, b.y, fmaf(a.y, b.x, acc.y));
    return acc;
}
// Bank-conflict-avoiding swizzle: fold address bits 4..7 into bits 0..3.
__device__ __forceinline__ int swz(int y) { return y ^ ((y >> 4) & 0xF); }

__global__ __launch_bounds__(NTHREADS, 1)
void qsim_kernel(const float* __restrict__ x, const float* __restrict__ params,
                 float* __restrict__ out, GateMasks gm)
{
    extern __shared__ float2 state[];          // 16384 float2 = 128 KB
    __shared__ float2 mats[2][NW][4];          // fused 2x2 per (layer, wire)
    __shared__ float wsum[NWARPS][NW];

    const int tid = threadIdx.x;
    const int b = blockIdx.x;

    // ---- 1. Fused gate matrices: M = RX(l2) * RZ(l1) * RY(l0 [+ x_w for layer 0])
    if (tid < 2 * NW) {
        const int l = tid / NW, w = tid % NW;
        const float* pp = params + (l * NW + w) * 3;
        float th = pp[0] + (l == 0 ? x[b * NW + w] : 0.0f);
        float s, c;   sincosf(0.5f * th, &s, &c);
        float sz, cz; sincosf(0.5f * pp[1], &sz, &cz);
        float sx, cx; sincosf(0.5f * pp[2], &sx, &cx);
        // RZ*RY rows: row0 scaled by e^{-i phi/2}=(cz,-sz), row1 by e^{+i phi/2}
        float2 r00 = make_float2(c * cz, -c * sz);
        float2 r01 = make_float2(-s * cz, s * sz);
        float2 r10 = make_float2(s * cz, s * sz);
        float2 r11 = make_float2(c * cz, c * sz);
        // RX = [[cx, -i sx], [-i sx, cx]];  (-i*sx)*(zx,zy) = (sx*zy, -sx*zx)
        mats[l][w][0] = make_float2(cx * r00.x + sx * r10.y, cx * r00.y - sx * r10.x);
        mats[l][w][1] = make_float2(cx * r01.x + sx * r11.y, cx * r01.y - sx * r11.x);
        mats[l][w][2] = make_float2(sx * r00.y + cx * r10.x, -sx * r00.x + cx * r10.y);
        mats[l][w][3] = make_float2(sx * r01.y + cx * r11.x, -sx * r01.x + cx * r11.y);
    }
    __syncthreads();

    // ---- 2. Pass A: build post-layer-0 product state directly in registers and
    //         apply layer-1 gates on virtual bits 9..13 (wires 4..0). No shared reads.
    {
        const int r = tid;  // complement basis {e0..e8}
        int m[5], base = 0;
#pragma unroll
        for (int i = 0; i < 5; i++) {
            m[i] = gm.colAinv[9 + i];
            base |= (__popc(r & gm.rowA[9 + i]) & 1) << i;
        }
        // fixed product over physical bits 0..7 (untouched by this group's masks)
        float2 p = make_float2(1.0f, 0.0f);
#pragma unroll
        for (int bb = 0; bb < 8; ++bb) {
            float2 col = ((r >> bb) & 1) ? mats[0][13 - bb][2] : mats[0][13 - bb][0];
            p = cmul(p, col);
        }
        float2 amp[32];
#pragma unroll
        for (int u = 0; u < 32; u++) {
            int ub = u ^ base;
            int y = r;
#pragma unroll
            for (int i = 0; i < 5; i++) if ((ub >> i) & 1) y ^= m[i];
            float2 v = p;
#pragma unroll
            for (int bb = 8; bb < 14; ++bb) {
                float2 col = ((y >> bb) & 1) ? mats[0][13 - bb][2] : mats[0][13 - bb][0];
                v = cmul(v, col);
            }
            amp[u] = v;
        }
        // butterflies: layer-1 gates, virtual bit 9+i == wire 4-i
#pragma unroll
        for (int i = 0; i < 5; i++) {
            const int w = 13 - (9 + i);
            float2 M00 = mats[1][w][0], M01 = mats[1][w][1];
            float2 M10 = mats[1][w][2], M11 = mats[1][w][3];
#pragma unroll
            for (int u = 0; u < 32; u++) {
                if (u & (1 << i)) continue;
                float2 a0 = amp[u], a1 = amp[u | (1 << i)];
                float2 n0 = cmul(M00, a0); n0 = cmadd(n0, M01, a1);
                float2 n1 = cmul(M10, a0); n1 = cmadd(n1, M11, a1);
                amp[u] = n0; amp[u | (1 << i)] = n1;
            }
        }
#pragma unroll
        for (int u = 0; u < 32; u++) {
            int ub = u ^ base;
            int y = r;
#pragma unroll
            for (int i = 0; i < 5; i++) if ((ub >> i) & 1) y ^= m[i];
            state[swz(y)] = amp[u];
        }
    }
    __syncthreads();

    // ---- 3. Pass B: layer-1 gates on virtual bits 4..8 (wires 9..5)
    {
        const int r = (tid & 0xF) | ((tid >> 4) << 9);  // complement {e0..e3, e9..e13}
        int m[5], base = 0;
#pragma unroll
        for (int i = 0; i < 5; i++) {
            m[i] = gm.colAinv[4 + i];
            base |= (__popc(r & gm.rowA[4 + i]) & 1) << i;
        }
        float2 amp[32];
#pragma unroll
        for (int u = 0; u < 32; u++) {
            int ub = u ^ base;
            int y = r;
#pragma unroll
            for (int i = 0; i < 5; i++) if ((ub >> i) & 1) y ^= m[i];
            amp[u] = state[swz(y)];
        }
#pragma unroll
        for (int i = 0; i < 5; i++) {
            const int w = 13 - (4 + i);
            float2 M00 = mats[1][w][0], M01 = mats[1][w][1];
            float2 M10 = mats[1][w][2], M11 = mats[1][w][3];
#pragma unroll
            for (int u = 0; u < 32; u++) {
                if (u & (1 << i)) continue;
                float2 a0 = amp[u], a1 = amp[u | (1 << i)];
                float2 n0 = cmul(M00, a0); n0 = cmadd(n0, M01, a1);
                float2 n1 = cmul(M10, a0); n1 = cmadd(n1, M11, a1);
                amp[u] = n0; amp[u | (1 << i)] = n1;
            }
        }
#pragma unroll
        for (int u = 0; u < 32; u++) {
            int ub = u ^ base;
            int y = r;
#pragma unroll
            for (int i = 0; i < 5; i++) if ((ub >> i) & 1) y ^= m[i];
            state[swz(y)] = amp[u];
        }
    }
    __syncthreads();

    // ---- 4. Pass C: layer-1 gates on virtual bits 0..3 (wires 13..10); 2 cosets/thread
#pragma unroll
    for (int it = 0; it < 2; ++it) {
        const int tt = tid + it * NTHREADS;
        const int r = tt << 4;  // complement {e4..e13}
        int m[4], base = 0;
#pragma unroll
        for (int i = 0; i < 4; i++) {
            m[i] = gm.colAinv[i];
            base |= (__popc(r & gm.rowA[i]) & 1) << i;
        }
        float2 amp[16];
#pragma unroll
        for (int u = 0; u < 16; u++) {
            int ub = u ^ base;
            int y = r;
#pragma unroll
            for (int i = 0; i < 4; i++) if ((ub >> i) & 1) y ^= m[i];
            amp[u] = state[swz(y)];
        }
#pragma unroll
        for (int i = 0; i < 4; i++) {
            const int w = 13 - i;
            float2 M00 = mats[1][w][0], M01 = mats[1][w][1];
            float2 M10 = mats[1][w][2], M11 = mats[1][w][3];
#pragma unroll
            for (int u = 0; u < 16; u++) {
                if (u & (1 << i)) continue;
                float2 a0 = amp[u], a1 = amp[u | (1 << i)];
                float2 n0 = cmul(M00, a0); n0 = cmadd(n0, M01, a1);
                float2 n1 = cmul(M10, a0); n1 = cmadd(n1, M11, a1);
                amp[u] = n0; amp[u | (1 << i)] = n1;
            }
        }
#pragma unroll
        for (int u = 0; u < 16; u++) {
            int ub = u ^ base;
            int y = r;
#pragma unroll
            for (int i = 0; i < 4; i++) if ((ub >> i) & 1) y ^= m[i];
            state[swz(y)] = amp[u];
        }
    }
    __syncthreads();

    // ---- 5. Measurement: <Z_w> with parity masks rowA2 (virtual frame after 2 entanglers)
    float acc[NW];
#pragma unroll
    for (int w = 0; w < NW; ++w) acc[w] = 0.0f;
#pragma unroll 4
    for (int k = 0; k < NSTATE / NTHREADS; ++k) {
        const int y = tid + (k << 9);
        float2 v = state[swz(y)];
        float pr = fmaf(v.x, v.x, v.y * v.y);
#pragma unroll
        for (int w = 0; w < NW; ++w) {
            acc[w] += (__popc(y & gm.rowA2[13 - w]) & 1) ? -pr : pr;
        }
    }
    const int lane = tid & 31, warp = tid >> 5;
#pragma unroll
    for (int w = 0; w < NW; ++w) {
        float v = acc[w];
#pragma unroll
        for (int off = 16; off; off >>= 1) v += __shfl_down_sync(0xFFFFFFFFu, v, off);
        if (lane == 0) wsum[warp][w] = v;
    }
    __syncthreads();
    if (tid < NW) {
        float s = 0.0f;
#pragma unroll
        for (int q = 0; q < NWARPS; ++q) s += wsum[q][tid];
        out[b * NW + tid] = s;
    }
}

// ---------------- host side ----------------

static GateMasks compute_masks()
{
    GateMasks g;
    unsigned R[NW];
    for (int j = 0; j < NW; j++) R[j] = 1u << j;
    // Entangler in time order: CNOT(w, w+1) for w=0..12, then CNOT(13, 0).
    // Wire w <-> bit (13 - w).  Left-multiply rule: R[bt] ^= R[bc].
    for (int w = 0; w < NW - 1; ++w) {
        int bc = NW - 1 - w;   // control bit
        int bt = NW - 2 - w;   // target bit
        R[bt] ^= R[bc];
    }
    R[NW - 1] ^= R[0];         // CNOT(13, 0): control bit 0, target bit 13
    for (int j = 0; j < NW; j++) g.rowA[j] = (int)R[j];

    // Gauss-Jordan inversion over GF(2): aug = [A | I]
    unsigned aug[NW];
    for (int j = 0; j < NW; j++) aug[j] = R[j] | (1u << (NW + j));
    for (int col = 0; col < NW; ++col) {
        int piv = -1;
        for (int rr = col; rr < NW; ++rr)
            if ((aug[rr] >> col) & 1u) { piv = rr; break; }
        unsigned tmp = aug[col]; aug[col] = aug[piv]; aug[piv] = tmp;
        for (int rr = 0; rr < NW; ++rr)
            if (rr != col && ((aug[rr] >> col) & 1u)) aug[rr] ^= aug[col];
    }
    for (int bcol = 0; bcol < NW; bcol++) {
        unsigned mcol = 0;
        for (int j = 0; j < NW; j++) mcol |= ((aug[j] >> (NW + bcol)) & 1u) << j;
        g.colAinv[bcol] = (int)mcol;
    }
    for (int k = 0; k < NW; k++) {
        unsigned rr = 0;
        for (int j = 0; j < NW; j++) if ((R[k] >> j) & 1u) rr ^= R[j];
        g.rowA2[k] = (int)rr;
    }
    return g;
}

extern "C" void kernel_launch(void* const* d_in, const int* in_sizes, int n_in,
                              void* d_out, int out_size)
{
    int i_x = 0, i_p = 1;
    if (n_in >= 2 && in_sizes[0] == 2 * NW * 3) { i_x = 1; i_p = 0; }  // params first
    const float* x = (const float*)d_in[i_x];
    const float* params = (const float*)d_in[i_p];
    float* out = (float*)d_out;

    const int batch = in_sizes[i_x] / NW;
    static const GateMasks gm = compute_masks();

    cudaFuncSetAttribute(qsim_kernel, cudaFuncAttributeMaxDynamicSharedMemorySize,
                         NSTATE * sizeof(float2));
    qsim_kernel<<<batch, NTHREADS, NSTATE * sizeof(float2)>>>(x, params, out, gm);
}